// round 15
// baseline (speedup 1.0000x reference)
#include <cuda_runtime.h>
#include <cuda_bf16.h>
#include <math.h>

#define BB 4
#define TT 16
#define HH 64
#define WW 64
#define CIN 32
#define COUT 64
#define GG 256

// Padded pixel space for implicit-GEMM conv
#define PW 66
#define PHW (PW*PW)            // 4356
#define PTOT (BB*PHW)          // 17424
#define NTILE 137              // ceil(17424/128)
#define PALLOC (NTILE*128)     // 17536
#define GUARD 128
#define HPX (PALLOC + 2*GUARD) // 17792

typedef unsigned long long u64;
typedef unsigned int u32;

// ---------------- device scratch (zero-initialized) -------------------------
__device__ float g_gx [(size_t)BB*TT*HH*WW*GG];       // input-conv gates (fp32)
__device__ float g_c  [(size_t)BB*HH*WW*COUT];        // cell state
// Ping-pong hidden state, padded layout, bf16 hi/lo split. Pads stay 0.
__device__ __align__(16) __nv_bfloat16 g_h_hi0[(size_t)HPX*COUT];
__device__ __align__(16) __nv_bfloat16 g_h_lo0[(size_t)HPX*COUT];
__device__ __align__(16) __nv_bfloat16 g_h_hi1[(size_t)HPX*COUT];
__device__ __align__(16) __nv_bfloat16 g_h_lo1[(size_t)HPX*COUT];
// Recurrent weights as col-major B: [tap][n=256][k=64], bf16 hi/lo
__device__ __align__(16) __nv_bfloat16 g_Bhi[9*256*64];
__device__ __align__(16) __nv_bfloat16 g_Blo[9*256*64];
// Split transposed weights for scalar input conv
__device__ float g_wk01[9*CIN*32*4];
__device__ float g_wk23[9*CIN*32*4];

// ---------------- helpers ----------------------------------------------------
__device__ __forceinline__ float hsig(float z) {
    return fminf(fmaxf(0.2f*z + 0.5f, 0.0f), 1.0f);
}
__device__ __forceinline__ void fma_x2(u64& acc, u64 s, u64 w) {
    asm("fma.rn.f32x2 %0, %1, %2, %3;" : "=l"(acc) : "l"(s), "l"(w), "l"(acc));
}
__device__ __forceinline__ u64 pack2(float s) {
    u64 r; asm("mov.b64 %0, {%1, %1};" : "=l"(r) : "f"(s)); return r;
}
__device__ __forceinline__ u32 smem_to_u32(const void* p) {
    u32 a; asm("{ .reg .u64 t; cvta.to.shared.u64 t, %1; cvt.u32.u64 %0, t; }" : "=r"(a) : "l"(p));
    return a;
}

#define LDSM_X4(r0, r1, r2, r3, addr) \
    asm volatile("ldmatrix.sync.aligned.m8n8.x4.shared.b16 {%0,%1,%2,%3}, [%4];" \
        : "=r"(r0), "=r"(r1), "=r"(r2), "=r"(r3) : "r"(addr))

#define MMA_BF16(c, a, b) \
    asm volatile("mma.sync.aligned.m16n8k16.row.col.f32.bf16.bf16.f32 " \
        "{%0,%1,%2,%3}, {%4,%5,%6,%7}, {%8,%9}, {%0,%1,%2,%3};" \
        : "+f"((c)[0]), "+f"((c)[1]), "+f"((c)[2]), "+f"((c)[3]) \
        : "r"((a)[0]), "r"((a)[1]), "r"((a)[2]), "r"((a)[3]), \
          "r"((b)[0]), "r"((b)[1]))

// ---------------- prep kernels ------------------------------------------------
__global__ __launch_bounds__(128)
void prep_weights(const float* __restrict__ wk)
{
    const int m = blockIdx.x * 128 + threadIdx.x;
    if (m < 9*CIN*32) {
        const int j  = m & 31;
        const int ci = (m >> 5) & 31;
        const int k  = m >> 10;
        const float* s = wk + ((size_t)(k*CIN + ci))*GG + 2*j;
        ((float4*)g_wk01)[m] = make_float4(s[0],   s[1],   s[64],  s[65]);
        ((float4*)g_wk23)[m] = make_float4(s[128], s[129], s[192], s[193]);
    }
}

__global__ __launch_bounds__(256)
void prep_rw_bf16(const float* __restrict__ rw)
{
    const int i = blockIdx.x * 256 + threadIdx.x;
    if (i >= 9*256*64) return;
    const int k   = i & 63;
    const int n   = (i >> 6) & 255;
    const int tap = i >> 14;
    const float v = rw[((size_t)(tap*COUT + k))*GG + n];
    const __nv_bfloat16 h = __float2bfloat16(v);
    g_Bhi[i] = h;
    g_Blo[i] = __float2bfloat16(v - __bfloat162float(h));
}

// ---------------- scalar input conv (round-12 winner, 2-timestep chunks) ------
#define CHUNK 4
#define TILE4 (9*CHUNK*32)

__global__ __launch_bounds__(128, 4)
void input_conv_kernel(const float* __restrict__ x,
                       const float* __restrict__ bias,
                       const int t0)
{
    __shared__ float4 s01[TILE4];
    __shared__ float4 s23[TILE4];

    const int tx   = threadIdx.x;
    const int lane = tx & 31;
    const int co0  = lane * 2;
    const int pg   = tx >> 5;
    const int bid  = blockIdx.x;
    const int t    = t0 + (bid >> 9);
    const int inner= bid & 511;
    const int b    = inner >> 7;
    const int bt   = b*TT + t;
    const int r    = inner & 127;
    const int py   = r >> 1;
    const int px0  = (r & 1) * 32 + pg * 8;
    const bool okL = (px0 > 0);
    const bool okR = (px0 < WW - 8);

    u64 acc[4][8];
    #pragma unroll
    for (int g = 0; g < 4; g++) {
        u64 bv = *(const u64*)(bias + g*COUT + co0);
        #pragma unroll
        for (int p = 0; p < 8; p++) acc[g][p] = bv;
    }

    const int iy0 = py - 1;
    const float* __restrict__ xbase = x + ((size_t)(bt*HH))*WW*CIN;

    #pragma unroll 1
    for (int cc = 0; cc < CIN; cc += CHUNK) {
        __syncthreads();
        #pragma unroll
        for (int i = tx; i < TILE4; i += 128) {
            const int tap  = i >> 7;
            const int rest = i & 127;
            const size_t src = (size_t)(tap*CIN + cc)*32 + rest;
            s01[i] = ((const float4*)g_wk01)[src];
            s23[i] = ((const float4*)g_wk23)[src];
        }
        __syncthreads();

        #pragma unroll
        for (int ky = 0; ky < 3; ky++) {
            const int iy = iy0 + ky;
            if ((unsigned)iy >= HH) continue;
            const float* __restrict__ xrow = xbase + ((size_t)iy*WW)*CIN;
            #pragma unroll
            for (int c4 = 0; c4 < CHUNK; c4++) {
                const int ci = cc + c4;
                u64 hv2[10];
                hv2[0] = okL ? pack2(xrow[(size_t)(px0-1)*CIN + ci]) : 0ULL;
                #pragma unroll
                for (int j = 1; j < 9; j++)
                    hv2[j] = pack2(xrow[(size_t)(px0-1+j)*CIN + ci]);
                hv2[9] = okR ? pack2(xrow[(size_t)(px0+8)*CIN + ci]) : 0ULL;
                #pragma unroll
                for (int kx = 0; kx < 3; kx++) {
                    const int sidx = ((ky*3+kx)*CHUNK + c4)*32 + lane;
                    const ulonglong2 wA = *reinterpret_cast<const ulonglong2*>(&s01[sidx]);
                    const ulonglong2 wB = *reinterpret_cast<const ulonglong2*>(&s23[sidx]);
                    #pragma unroll
                    for (int p = 0; p < 8; p++) {
                        const u64 s2 = hv2[p + kx];
                        fma_x2(acc[0][p], s2, wA.x);
                        fma_x2(acc[1][p], s2, wA.y);
                        fma_x2(acc[2][p], s2, wB.x);
                        fma_x2(acc[3][p], s2, wB.y);
                    }
                }
            }
        }
    }

    const size_t rowbase = ((size_t)bt*HH + py)*WW;
    #pragma unroll
    for (int p = 0; p < 8; p++) {
        float* __restrict__ o = g_gx + (rowbase + px0 + p)*GG + co0;
        *(u64*)(o + 0*COUT) = acc[0][p];
        *(u64*)(o + 1*COUT) = acc[1][p];
        *(u64*)(o + 2*COUT) = acc[2][p];
        *(u64*)(o + 3*COUT) = acc[3][p];
    }
}

// ---------------- HMMA recurrent GEMM + fused LSTM epilogue -------------------
// smem: A window hi/lo (264 rows x 128B) + B tile hi/lo (256 rows x 128B).
// Epilogue reuses smem as fp32 acc [128][258].
#define SM_A_HI 0
#define SM_A_LO 33792
#define SM_B_HI 67584
#define SM_B_LO 100352
#define GEMM_SMEM 133120
#define EPI_STRIDE 258

__device__ __forceinline__ u32 swz(u32 row, u32 chunk) {
    return row*128u + ((chunk ^ (row & 7u)) << 4);
}

__global__ __launch_bounds__(512, 1)
void step_gemm(float* __restrict__ y, const int t,
               const float* __restrict__ gamma, const float* __restrict__ beta,
               const float* __restrict__ mmean, const float* __restrict__ mvar)
{
    extern __shared__ char smem[];
    const u32 sbase = smem_to_u32(smem);
    const int tid  = threadIdx.x;
    const int wid  = tid >> 5;
    const int lane = tid & 31;
    const int tile = blockIdx.x;
    const int m_base = tile * 128;

    const __nv_bfloat16* __restrict__ ph_hi = (t & 1) ? g_h_hi0 : g_h_hi1;
    const __nv_bfloat16* __restrict__ ph_lo = (t & 1) ? g_h_lo0 : g_h_lo1;

    // Fill A window: padded-h rows [m_base-67, m_base+197) (264 rows)
    {
        const size_t src0 = (size_t)(GUARD + m_base - 67) * COUT;
        for (int i = tid; i < 264*8; i += 512) {
            const int row = i >> 3, c = i & 7;
            const u32 d = swz((u32)row, (u32)c);
            *(uint4*)(smem + SM_A_HI + d) =
                *(const uint4*)(ph_hi + src0 + (size_t)row*COUT + c*8);
            *(uint4*)(smem + SM_A_LO + d) =
                *(const uint4*)(ph_lo + src0 + (size_t)row*COUT + c*8);
        }
    }

    const int wm = wid >> 3;            // 0..1  (m64 tile)
    const int wn = wid & 7;             // 0..7  (n32 tile)
    const int n0 = wn * 32;

    const int lmat = lane >> 3;
    const int lrow = lane & 7;
    const int aRowLane  = wm*64 + 67 + (lmat & 1)*8 + lrow;
    const int aChunkSel = lmat >> 1;
    const int bRowLane  = n0 + (lmat >> 1)*8 + lrow;
    const int bChunkSel = lmat & 1;

    float acc[4][4][4];
    #pragma unroll
    for (int ms = 0; ms < 4; ms++)
        #pragma unroll
        for (int nf = 0; nf < 4; nf++)
            #pragma unroll
            for (int e = 0; e < 4; e++) acc[ms][nf][e] = 0.0f;

    const int aoff[9] = {-PW-1, -PW, -PW+1, -1, 0, 1, PW-1, PW, PW+1};

    __syncthreads();   // A window ready

    #pragma unroll 1
    for (int tap = 0; tap < 9; tap++) {
        if (tap) __syncthreads();
        for (int i = tid; i < 256*8; i += 512) {
            const int row = i >> 3, c = i & 7;
            const u32 d = swz((u32)row, (u32)c);
            const size_t src = (size_t)tap*16384 + (size_t)row*64 + c*8;
            *(uint4*)(smem + SM_B_HI + d) = *(const uint4*)(g_Bhi + src);
            *(uint4*)(smem + SM_B_LO + d) = *(const uint4*)(g_Blo + src);
        }
        __syncthreads();

        #pragma unroll
        for (int kc = 0; kc < 4; kc++) {
            u32 ah[4][4];
            #pragma unroll
            for (int ms = 0; ms < 4; ms++) {
                const int wrow = aRowLane + ms*16 + aoff[tap];
                const u32 addr = sbase + SM_A_HI + swz((u32)wrow, (u32)(2*kc + aChunkSel));
                LDSM_X4(ah[ms][0], ah[ms][1], ah[ms][2], ah[ms][3], addr);
            }
            u32 bb[4][2];
            #pragma unroll
            for (int q = 0; q < 2; q++) {
                const u32 addr = sbase + SM_B_HI +
                    swz((u32)(bRowLane + q*16), (u32)(2*kc + bChunkSel));
                LDSM_X4(bb[2*q][0], bb[2*q][1], bb[2*q+1][0], bb[2*q+1][1], addr);
            }
            #pragma unroll
            for (int ms = 0; ms < 4; ms++)
                #pragma unroll
                for (int nf = 0; nf < 4; nf++)
                    MMA_BF16(acc[ms][nf], ah[ms], bb[nf]);

            #pragma unroll
            for (int q = 0; q < 2; q++) {
                const u32 addr = sbase + SM_B_LO +
                    swz((u32)(bRowLane + q*16), (u32)(2*kc + bChunkSel));
                LDSM_X4(bb[2*q][0], bb[2*q][1], bb[2*q+1][0], bb[2*q+1][1], addr);
            }
            #pragma unroll
            for (int ms = 0; ms < 4; ms++)
                #pragma unroll
                for (int nf = 0; nf < 4; nf++)
                    MMA_BF16(acc[ms][nf], ah[ms], bb[nf]);

            #pragma unroll
            for (int ms = 0; ms < 4; ms++) {
                const int wrow = aRowLane + ms*16 + aoff[tap];
                const u32 addr = sbase + SM_A_LO + swz((u32)wrow, (u32)(2*kc + aChunkSel));
                LDSM_X4(ah[ms][0], ah[ms][1], ah[ms][2], ah[ms][3], addr);
            }
            #pragma unroll
            for (int q = 0; q < 2; q++) {
                const u32 addr = sbase + SM_B_HI +
                    swz((u32)(bRowLane + q*16), (u32)(2*kc + bChunkSel));
                LDSM_X4(bb[2*q][0], bb[2*q][1], bb[2*q+1][0], bb[2*q+1][1], addr);
            }
            #pragma unroll
            for (int ms = 0; ms < 4; ms++)
                #pragma unroll
                for (int nf = 0; nf < 4; nf++)
                    MMA_BF16(acc[ms][nf], ah[ms], bb[nf]);
        }
    }

    // ---- fused epilogue: stage acc in smem, then LSTM math -------------------
    __syncthreads();                      // all A/B reads done; smem reusable
    float* __restrict__ sacc = (float*)smem;
    {
        const int rl = wm*64 + (lane >> 2);
        const int cl = n0 + (lane & 3)*2;
        #pragma unroll
        for (int ms = 0; ms < 4; ms++) {
            #pragma unroll
            for (int nf = 0; nf < 4; nf++) {
                const int row0 = rl + ms*16;
                const int col  = cl + nf*8;
                sacc[(size_t)row0*EPI_STRIDE + col]     = acc[ms][nf][0];
                sacc[(size_t)row0*EPI_STRIDE + col + 1] = acc[ms][nf][1];
                sacc[(size_t)(row0+8)*EPI_STRIDE + col]     = acc[ms][nf][2];
                sacc[(size_t)(row0+8)*EPI_STRIDE + col + 1] = acc[ms][nf][3];
            }
        }
    }
    __syncthreads();

    // 512 threads: row = tid>>2 (128 rows), 16 channels each
    const int r   = tid >> 2;
    const int ch0 = (tid & 3) * 16;
    const int pp  = m_base + r;
    const int b   = pp / PHW;
    const int rm  = pp - b*PHW;
    const int yy  = rm / PW;
    const int xx  = rm - yy*PW;
    const bool inter = (pp < PTOT) && (yy >= 1) && (yy <= HH) && (xx >= 1) && (xx <= WW);

    if (inter) {
        const int rem = (yy-1)*WW + (xx-1);
        const size_t gxb = ((size_t)(b*TT + t)*4096 + rem)*GG;
        const size_t cb  = ((size_t)b*4096 + rem)*COUT;
        const size_t ybb = ((size_t)(b*TT + t)*4096 + rem)*COUT;
        __nv_bfloat16* __restrict__ nh_hi = ((t & 1) ? g_h_hi1 : g_h_hi0) + (size_t)(GUARD + pp)*COUT;
        __nv_bfloat16* __restrict__ nh_lo = ((t & 1) ? g_h_lo1 : g_h_lo0) + (size_t)(GUARD + pp)*COUT;
        const float* __restrict__ srow = sacc + (size_t)r*EPI_STRIDE;

        #pragma unroll 4
        for (int c = 0; c < 16; c++) {
            const int ch = ch0 + c;
            const float gi = g_gx[gxb + 0*COUT + ch] + srow[0*COUT + ch];
            const float gf = g_gx[gxb + 1*COUT + ch] + srow[1*COUT + ch];
            const float gg = g_gx[gxb + 2*COUT + ch] + srow[2*COUT + ch];
            const float go = g_gx[gxb + 3*COUT + ch] + srow[3*COUT + ch];
            const float iv = hsig(gi), fv = hsig(gf), ov = hsig(go);
            const float cold = g_c[cb + ch];
            const float cn = fv*cold + iv*tanhf(gg);
            g_c[cb + ch] = cn;
            const float hval = ov * tanhf(cn);
            const __nv_bfloat16 hh = __float2bfloat16(hval);
            nh_hi[ch] = hh;
            nh_lo[ch] = __float2bfloat16(hval - __bfloat162float(hh));
            const float inv = gamma[ch] * rsqrtf(mvar[ch] + 1e-3f);
            y[ybb + ch] = hval*inv + (beta[ch] - mmean[ch]*inv);
        }
    }
}

// ---------------- t=0 epilogue (no recurrent conv) -----------------------------
__global__ __launch_bounds__(256)
void step0_epi(float* __restrict__ y,
               const float* __restrict__ gamma, const float* __restrict__ beta,
               const float* __restrict__ mmean, const float* __restrict__ mvar)
{
    const int gid = blockIdx.x * 256 + threadIdx.x;
    const int px  = gid >> 6;
    const int ch  = gid & 63;
    const int b   = px >> 12;
    const int rem = px & 4095;
    const int yy  = rem >> 6, xx = rem & 63;
    const int pad = b*PHW + (yy + 1)*PW + (xx + 1);

    const size_t gxb = ((size_t)(b*TT)*4096 + rem)*GG + ch;
    const float gi = g_gx[gxb + 0*COUT];
    const float gf = g_gx[gxb + 1*COUT];
    const float gg = g_gx[gxb + 2*COUT];
    const float go = g_gx[gxb + 3*COUT];
    (void)gf;
    const float iv = hsig(gi), ov = hsig(go);
    const float cn = iv*tanhf(gg);
    g_c[(size_t)px*COUT + ch] = cn;
    const float hval = ov * tanhf(cn);

    const __nv_bfloat16 hh = __float2bfloat16(hval);
    g_h_hi0[(size_t)(GUARD + pad)*COUT + ch] = hh;
    g_h_lo0[(size_t)(GUARD + pad)*COUT + ch] = __float2bfloat16(hval - __bfloat162float(hh));

    const float inv = gamma[ch] * rsqrtf(mvar[ch] + 1e-3f);
    y[((size_t)(b*TT)*4096 + rem)*COUT + ch] = hval*inv + (beta[ch] - mmean[ch]*inv);
}

// ---------------- host ----------------------------------------------------------
extern "C" void kernel_launch(void* const* d_in, const int* in_sizes, int n_in,
                              void* d_out, int out_size)
{
    const float* x      = (const float*)d_in[0];
    const float* wk     = (const float*)d_in[1];
    const float* rw     = (const float*)d_in[2];
    const float* bias   = (const float*)d_in[3];
    const float* gamma  = (const float*)d_in[4];
    const float* beta   = (const float*)d_in[5];
    const float* mmean  = (const float*)d_in[6];
    const float* mvar   = (const float*)d_in[7];
    float* y = (float*)d_out;

    cudaFuncSetAttribute(step_gemm, cudaFuncAttributeMaxDynamicSharedMemorySize, GEMM_SMEM);

    cudaStream_t s2;
    cudaStreamCreateWithFlags(&s2, cudaStreamNonBlocking);
    cudaEvent_t evPrep;
    cudaEvent_t evConv[8];
    cudaEventCreateWithFlags(&evPrep, cudaEventDisableTiming);
    for (int c = 0; c < 8; c++)
        cudaEventCreateWithFlags(&evConv[c], cudaEventDisableTiming);

    // Prep on main stream.
    prep_weights<<<(9*CIN*32 + 127)/128, 128>>>(wk);
    prep_rw_bf16<<<(9*256*64)/256, 256>>>(rw);
    cudaEventRecord(evPrep, 0);

    // Fork: input convs in 8 chunks of 2 timesteps on s2.
    cudaStreamWaitEvent(s2, evPrep, 0);
    for (int c = 0; c < 8; c++) {
        input_conv_kernel<<<2*512, 128, 0, s2>>>(x, bias, c*2);
        cudaEventRecord(evConv[c], s2);
    }

    // Main stream recurrence: step0 epilogue, then 15 fused gemm+epi steps.
    cudaStreamWaitEvent(0, evConv[0], 0);
    step0_epi<<<(BB*HH*WW*COUT)/256, 256>>>(y, gamma, beta, mmean, mvar);
    for (int t = 1; t < TT; t++) {
        if ((t & 1) == 0) cudaStreamWaitEvent(0, evConv[t >> 1], 0);
        step_gemm<<<NTILE, 512, GEMM_SMEM>>>(y, t, gamma, beta, mmean, mvar);
    }
}

// round 16
// speedup vs baseline: 1.5183x; 1.5183x over previous
#include <cuda_runtime.h>
#include <cuda_bf16.h>
#include <math.h>

#define BB 4
#define TT 16
#define HH 64
#define WW 64
#define CIN 32
#define COUT 64
#define GG 256

// Padded pixel space for the recurrent GEMM (h)
#define PW 66
#define PHW (PW*PW)            // 4356
#define PTOT (BB*PHW)          // 17424
#define NTILE 137              // ceil(17424/128)
#define PALLOC (NTILE*128)     // 17536
#define GUARD 128
#define HPX (PALLOC + 2*GUARD) // 17792

// Padded pixel space for the input-conv GEMM (x), t-major images, tile-aligned
#define PHW_AL 4480            // 35 tiles of 128
#define XIMG (BB*TT)           // 64 images
#define PALLOC_X (XIMG*PHW_AL) // 286720
#define XGUARD 128
#define XTILES (PALLOC_X/128)  // 2240
#define CHTILES (XTILES/4)     // 560 tiles per 4-timestep chunk

typedef unsigned long long u64;
typedef unsigned int u32;

// ---------------- device scratch (zero-initialized) -------------------------
__device__ float g_gxp[(size_t)PALLOC_X*GG];          // input-conv gates, padded (fp32)
__device__ float g_rec[(size_t)PALLOC*GG];            // recurrent-conv gates (fp32)
__device__ float g_c  [(size_t)BB*HH*WW*COUT];        // cell state
// Ping-pong hidden state, padded, bf16 hi/lo split. Pads stay 0.
__device__ __align__(16) __nv_bfloat16 g_h_hi0[(size_t)HPX*COUT];
__device__ __align__(16) __nv_bfloat16 g_h_lo0[(size_t)HPX*COUT];
__device__ __align__(16) __nv_bfloat16 g_h_hi1[(size_t)HPX*COUT];
__device__ __align__(16) __nv_bfloat16 g_h_lo1[(size_t)HPX*COUT];
// Padded x, bf16 hi/lo split. Pads stay 0.
__device__ __align__(16) __nv_bfloat16 g_x_hi[(size_t)(PALLOC_X + 2*XGUARD)*CIN];
__device__ __align__(16) __nv_bfloat16 g_x_lo[(size_t)(PALLOC_X + 2*XGUARD)*CIN];
// Recurrent weights: [tap][n=256][k=64] bf16 hi/lo
__device__ __align__(16) __nv_bfloat16 g_Bhi[9*256*64];
__device__ __align__(16) __nv_bfloat16 g_Blo[9*256*64];
// Input weights: [tap][n=256][k=32] bf16 hi/lo
__device__ __align__(16) __nv_bfloat16 g_Whi[9*256*32];
__device__ __align__(16) __nv_bfloat16 g_Wlo[9*256*32];

// ---------------- helpers ----------------------------------------------------
__device__ __forceinline__ float hsig(float z) {
    return fminf(fmaxf(0.2f*z + 0.5f, 0.0f), 1.0f);
}
__device__ __forceinline__ u32 smem_to_u32(const void* p) {
    u32 a; asm("{ .reg .u64 t; cvta.to.shared.u64 t, %1; cvt.u32.u64 %0, t; }" : "=r"(a) : "l"(p));
    return a;
}

#define LDSM_X4(r0, r1, r2, r3, addr) \
    asm volatile("ldmatrix.sync.aligned.m8n8.x4.shared.b16 {%0,%1,%2,%3}, [%4];" \
        : "=r"(r0), "=r"(r1), "=r"(r2), "=r"(r3) : "r"(addr))

#define MMA_BF16(c, a, b) \
    asm volatile("mma.sync.aligned.m16n8k16.row.col.f32.bf16.bf16.f32 " \
        "{%0,%1,%2,%3}, {%4,%5,%6,%7}, {%8,%9}, {%0,%1,%2,%3};" \
        : "+f"((c)[0]), "+f"((c)[1]), "+f"((c)[2]), "+f"((c)[3]) \
        : "r"((a)[0]), "r"((a)[1]), "r"((a)[2]), "r"((a)[3]), \
          "r"((b)[0]), "r"((b)[1]))

// 128B-row swizzle (rec GEMM) and 64B-row swizzle (conv GEMM)
__device__ __forceinline__ u32 swz(u32 row, u32 chunk) {
    return row*128u + ((chunk ^ (row & 7u)) << 4);
}
__device__ __forceinline__ u32 swz32(u32 row, u32 chunk) {
    return row*64u + ((chunk ^ (row & 3u)) << 4);
}

// ---------------- prep kernels ------------------------------------------------
__global__ __launch_bounds__(256)
void prep_rw_bf16(const float* __restrict__ rw)
{
    const int i = blockIdx.x * 256 + threadIdx.x;
    if (i >= 9*256*64) return;
    const int k   = i & 63;
    const int n   = (i >> 6) & 255;
    const int tap = i >> 14;
    const float v = rw[((size_t)(tap*COUT + k))*GG + n];
    const __nv_bfloat16 h = __float2bfloat16(v);
    g_Bhi[i] = h;
    g_Blo[i] = __float2bfloat16(v - __bfloat162float(h));
}

__global__ __launch_bounds__(256)
void prep_wk_bf16(const float* __restrict__ wk)
{
    const int i = blockIdx.x * 256 + threadIdx.x;
    if (i >= 9*256*32) return;
    const int k   = i & 31;
    const int n   = (i >> 5) & 255;
    const int tap = i >> 13;
    const float v = wk[((size_t)(tap*CIN + k))*GG + n];
    const __nv_bfloat16 h = __float2bfloat16(v);
    g_Whi[i] = h;
    g_Wlo[i] = __float2bfloat16(v - __bfloat162float(h));
}

// x (fp32 NHWC, image idx b*TT+t) -> padded bf16 hi/lo, image idx t*BB+b
__global__ __launch_bounds__(256)
void prep_x(const float* __restrict__ x)
{
    const int gid = blockIdx.x * 256 + threadIdx.x;   // 1,048,576 threads
    const int opx = gid >> 2;                          // original pixel
    const int grp = gid & 3;                           // 8-channel group
    const int bt  = opx >> 12;
    const int b   = bt >> 4;
    const int t   = bt & 15;
    const int rem = opx & 4095;
    const int yy  = rem >> 6, xx = rem & 63;
    const size_t dst = ((size_t)(XGUARD + (t*BB + b)*PHW_AL + (yy+1)*PW + (xx+1)))*CIN + grp*8;

    const float4 v0 = *(const float4*)(x + (size_t)opx*CIN + grp*8);
    const float4 v1 = *(const float4*)(x + (size_t)opx*CIN + grp*8 + 4);
    __nv_bfloat16 hi[8], lo[8];
    const float vs[8] = {v0.x, v0.y, v0.z, v0.w, v1.x, v1.y, v1.z, v1.w};
    #pragma unroll
    for (int j = 0; j < 8; j++) {
        hi[j] = __float2bfloat16(vs[j]);
        lo[j] = __float2bfloat16(vs[j] - __bfloat162float(hi[j]));
    }
    *(uint4*)(g_x_hi + dst) = *(const uint4*)hi;
    *(uint4*)(g_x_lo + dst) = *(const uint4*)lo;
}

// ---------------- input-conv HMMA GEMM (K=32, 64B rows) ------------------------
#define CA_HI 0
#define CA_LO 16896
#define CB_HI 33792
#define CB_LO 50176
#define CONV_SMEM 66560

__global__ __launch_bounds__(512, 1)
void conv_gemm(const int gtile0)
{
    extern __shared__ char smem[];
    const u32 sbase = smem_to_u32(smem);
    const int tid  = threadIdx.x;
    const int wid  = tid >> 5;
    const int lane = tid & 31;
    const int m_base = (gtile0 + blockIdx.x) * 128;

    // Fill A window: rows [m_base-67, m_base+197), 64B each, hi+lo
    for (int i = tid; i < 264*4; i += 512) {
        const int row = i >> 2, c = i & 3;
        const u32 d = swz32((u32)row, (u32)c);
        const size_t src = ((size_t)(XGUARD + m_base - 67 + row))*CIN + c*8;
        *(uint4*)(smem + CA_HI + d) = *(const uint4*)(g_x_hi + src);
        *(uint4*)(smem + CA_LO + d) = *(const uint4*)(g_x_lo + src);
    }

    const int wm = wid >> 3;
    const int wn = wid & 7;
    const int n0 = wn * 32;
    const int lmat = lane >> 3;
    const int lrow = lane & 7;
    const int aRowLane  = wm*64 + 67 + (lmat & 1)*8 + lrow;
    const int aChunkSel = lmat >> 1;
    const int bRowLane  = n0 + (lmat >> 1)*8 + lrow;
    const int bChunkSel = lmat & 1;

    float acc[4][4][4];
    #pragma unroll
    for (int ms = 0; ms < 4; ms++)
        #pragma unroll
        for (int nf = 0; nf < 4; nf++)
            #pragma unroll
            for (int e = 0; e < 4; e++) acc[ms][nf][e] = 0.0f;

    const int aoff[9] = {-PW-1, -PW, -PW+1, -1, 0, 1, PW-1, PW, PW+1};

    __syncthreads();

    #pragma unroll 1
    for (int tap = 0; tap < 9; tap++) {
        if (tap) __syncthreads();
        for (int i = tid; i < 256*4; i += 512) {
            const int row = i >> 2, c = i & 3;
            const u32 d = swz32((u32)row, (u32)c);
            const size_t src = (size_t)tap*8192 + (size_t)row*CIN + c*8;
            *(uint4*)(smem + CB_HI + d) = *(const uint4*)(g_Whi + src);
            *(uint4*)(smem + CB_LO + d) = *(const uint4*)(g_Wlo + src);
        }
        __syncthreads();

        #pragma unroll
        for (int kc = 0; kc < 2; kc++) {
            u32 ah[4][4];
            #pragma unroll
            for (int ms = 0; ms < 4; ms++) {
                const int wrow = aRowLane + ms*16 + aoff[tap];
                const u32 addr = sbase + CA_HI + swz32((u32)wrow, (u32)(2*kc + aChunkSel));
                LDSM_X4(ah[ms][0], ah[ms][1], ah[ms][2], ah[ms][3], addr);
            }
            u32 bb[4][2];
            #pragma unroll
            for (int q = 0; q < 2; q++) {
                const u32 addr = sbase + CB_HI +
                    swz32((u32)(bRowLane + q*16), (u32)(2*kc + bChunkSel));
                LDSM_X4(bb[2*q][0], bb[2*q][1], bb[2*q+1][0], bb[2*q+1][1], addr);
            }
            #pragma unroll
            for (int ms = 0; ms < 4; ms++)
                #pragma unroll
                for (int nf = 0; nf < 4; nf++)
                    MMA_BF16(acc[ms][nf], ah[ms], bb[nf]);

            #pragma unroll
            for (int q = 0; q < 2; q++) {
                const u32 addr = sbase + CB_LO +
                    swz32((u32)(bRowLane + q*16), (u32)(2*kc + bChunkSel));
                LDSM_X4(bb[2*q][0], bb[2*q][1], bb[2*q+1][0], bb[2*q+1][1], addr);
            }
            #pragma unroll
            for (int ms = 0; ms < 4; ms++)
                #pragma unroll
                for (int nf = 0; nf < 4; nf++)
                    MMA_BF16(acc[ms][nf], ah[ms], bb[nf]);

            #pragma unroll
            for (int ms = 0; ms < 4; ms++) {
                const int wrow = aRowLane + ms*16 + aoff[tap];
                const u32 addr = sbase + CA_LO + swz32((u32)wrow, (u32)(2*kc + aChunkSel));
                LDSM_X4(ah[ms][0], ah[ms][1], ah[ms][2], ah[ms][3], addr);
            }
            #pragma unroll
            for (int q = 0; q < 2; q++) {
                const u32 addr = sbase + CB_HI +
                    swz32((u32)(bRowLane + q*16), (u32)(2*kc + bChunkSel));
                LDSM_X4(bb[2*q][0], bb[2*q][1], bb[2*q+1][0], bb[2*q+1][1], addr);
            }
            #pragma unroll
            for (int ms = 0; ms < 4; ms++)
                #pragma unroll
                for (int nf = 0; nf < 4; nf++)
                    MMA_BF16(acc[ms][nf], ah[ms], bb[nf]);
        }
    }

    const int rbase = m_base + wm*64 + (lane >> 2);
    const int cbase = n0 + (lane & 3)*2;
    #pragma unroll
    for (int ms = 0; ms < 4; ms++) {
        #pragma unroll
        for (int nf = 0; nf < 4; nf++) {
            float* p0 = g_gxp + (size_t)(rbase + ms*16    )*GG + cbase + nf*8;
            float* p1 = g_gxp + (size_t)(rbase + ms*16 + 8)*GG + cbase + nf*8;
            *(float2*)p0 = make_float2(acc[ms][nf][0], acc[ms][nf][1]);
            *(float2*)p1 = make_float2(acc[ms][nf][2], acc[ms][nf][3]);
        }
    }
}

// ---------------- recurrent HMMA GEMM (R14 winner, unchanged) ------------------
#define SM_A_HI 0
#define SM_A_LO 33792
#define SM_B_HI 67584
#define SM_B_LO 100352
#define GEMM_SMEM 133120

__global__ __launch_bounds__(512, 1)
void step_gemm(const int t)
{
    extern __shared__ char smem[];
    const u32 sbase = smem_to_u32(smem);
    const int tid  = threadIdx.x;
    const int wid  = tid >> 5;
    const int lane = tid & 31;
    const int tile = blockIdx.x;
    const int m_base = tile * 128;

    const __nv_bfloat16* __restrict__ ph_hi = (t & 1) ? g_h_hi0 : g_h_hi1;
    const __nv_bfloat16* __restrict__ ph_lo = (t & 1) ? g_h_lo0 : g_h_lo1;

    {
        const size_t src0 = (size_t)(GUARD + m_base - 67) * COUT;
        for (int i = tid; i < 264*8; i += 512) {
            const int row = i >> 3, c = i & 7;
            const u32 d = swz((u32)row, (u32)c);
            *(uint4*)(smem + SM_A_HI + d) =
                *(const uint4*)(ph_hi + src0 + (size_t)row*COUT + c*8);
            *(uint4*)(smem + SM_A_LO + d) =
                *(const uint4*)(ph_lo + src0 + (size_t)row*COUT + c*8);
        }
    }

    const int wm = wid >> 3;
    const int wn = wid & 7;
    const int n0 = wn * 32;
    const int lmat = lane >> 3;
    const int lrow = lane & 7;
    const int aRowLane  = wm*64 + 67 + (lmat & 1)*8 + lrow;
    const int aChunkSel = lmat >> 1;
    const int bRowLane  = n0 + (lmat >> 1)*8 + lrow;
    const int bChunkSel = lmat & 1;

    float acc[4][4][4];
    #pragma unroll
    for (int ms = 0; ms < 4; ms++)
        #pragma unroll
        for (int nf = 0; nf < 4; nf++)
            #pragma unroll
            for (int e = 0; e < 4; e++) acc[ms][nf][e] = 0.0f;

    const int aoff[9] = {-PW-1, -PW, -PW+1, -1, 0, 1, PW-1, PW, PW+1};

    __syncthreads();

    #pragma unroll 1
    for (int tap = 0; tap < 9; tap++) {
        if (tap) __syncthreads();
        for (int i = tid; i < 256*8; i += 512) {
            const int row = i >> 3, c = i & 7;
            const u32 d = swz((u32)row, (u32)c);
            const size_t src = (size_t)tap*16384 + (size_t)row*64 + c*8;
            *(uint4*)(smem + SM_B_HI + d) = *(const uint4*)(g_Bhi + src);
            *(uint4*)(smem + SM_B_LO + d) = *(const uint4*)(g_Blo + src);
        }
        __syncthreads();

        #pragma unroll
        for (int kc = 0; kc < 4; kc++) {
            u32 ah[4][4];
            #pragma unroll
            for (int ms = 0; ms < 4; ms++) {
                const int wrow = aRowLane + ms*16 + aoff[tap];
                const u32 addr = sbase + SM_A_HI + swz((u32)wrow, (u32)(2*kc + aChunkSel));
                LDSM_X4(ah[ms][0], ah[ms][1], ah[ms][2], ah[ms][3], addr);
            }
            u32 bb[4][2];
            #pragma unroll
            for (int q = 0; q < 2; q++) {
                const u32 addr = sbase + SM_B_HI +
                    swz((u32)(bRowLane + q*16), (u32)(2*kc + bChunkSel));
                LDSM_X4(bb[2*q][0], bb[2*q][1], bb[2*q+1][0], bb[2*q+1][1], addr);
            }
            #pragma unroll
            for (int ms = 0; ms < 4; ms++)
                #pragma unroll
                for (int nf = 0; nf < 4; nf++)
                    MMA_BF16(acc[ms][nf], ah[ms], bb[nf]);

            #pragma unroll
            for (int q = 0; q < 2; q++) {
                const u32 addr = sbase + SM_B_LO +
                    swz((u32)(bRowLane + q*16), (u32)(2*kc + bChunkSel));
                LDSM_X4(bb[2*q][0], bb[2*q][1], bb[2*q+1][0], bb[2*q+1][1], addr);
            }
            #pragma unroll
            for (int ms = 0; ms < 4; ms++)
                #pragma unroll
                for (int nf = 0; nf < 4; nf++)
                    MMA_BF16(acc[ms][nf], ah[ms], bb[nf]);

            #pragma unroll
            for (int ms = 0; ms < 4; ms++) {
                const int wrow = aRowLane + ms*16 + aoff[tap];
                const u32 addr = sbase + SM_A_LO + swz((u32)wrow, (u32)(2*kc + aChunkSel));
                LDSM_X4(ah[ms][0], ah[ms][1], ah[ms][2], ah[ms][3], addr);
            }
            #pragma unroll
            for (int q = 0; q < 2; q++) {
                const u32 addr = sbase + SM_B_HI +
                    swz((u32)(bRowLane + q*16), (u32)(2*kc + bChunkSel));
                LDSM_X4(bb[2*q][0], bb[2*q][1], bb[2*q+1][0], bb[2*q+1][1], addr);
            }
            #pragma unroll
            for (int ms = 0; ms < 4; ms++)
                #pragma unroll
                for (int nf = 0; nf < 4; nf++)
                    MMA_BF16(acc[ms][nf], ah[ms], bb[nf]);
        }
    }

    const int rbase = m_base + wm*64 + (lane >> 2);
    const int cbase = n0 + (lane & 3)*2;
    #pragma unroll
    for (int ms = 0; ms < 4; ms++) {
        #pragma unroll
        for (int nf = 0; nf < 4; nf++) {
            float* p0 = g_rec + (size_t)(rbase + ms*16    )*GG + cbase + nf*8;
            float* p1 = g_rec + (size_t)(rbase + ms*16 + 8)*GG + cbase + nf*8;
            *(float2*)p0 = make_float2(acc[ms][nf][0], acc[ms][nf][1]);
            *(float2*)p1 = make_float2(acc[ms][nf][2], acc[ms][nf][3]);
        }
    }
}

// ---------------- LSTM epilogue (high-occupancy, R14 style + bias) -------------
template<bool FIRST>
__global__ __launch_bounds__(256)
void step_epi(float* __restrict__ y, const int t,
              const float* __restrict__ bias,
              const float* __restrict__ gamma, const float* __restrict__ beta,
              const float* __restrict__ mmean, const float* __restrict__ mvar)
{
    const int gid = blockIdx.x * 256 + threadIdx.x;
    const int px  = gid >> 6;
    const int ch  = gid & 63;
    const int b   = px >> 12;
    const int rem = px & 4095;
    const int yy  = rem >> 6, xx = rem & 63;
    const int pind = (yy + 1)*PW + (xx + 1);
    const int pad  = b*PHW + pind;

    const size_t gxb = ((size_t)(t*BB + b)*PHW_AL + pind)*GG + ch;
    float gi = g_gxp[gxb + 0*COUT] + bias[0*COUT + ch];
    float gf = g_gxp[gxb + 1*COUT] + bias[1*COUT + ch];
    float gg = g_gxp[gxb + 2*COUT] + bias[2*COUT + ch];
    float go = g_gxp[gxb + 3*COUT] + bias[3*COUT + ch];
    if (!FIRST) {
        const size_t rb = (size_t)pad*GG + ch;
        gi += g_rec[rb + 0*COUT];
        gf += g_rec[rb + 1*COUT];
        gg += g_rec[rb + 2*COUT];
        go += g_rec[rb + 3*COUT];
    }
    const float iv = hsig(gi), fv = hsig(gf), ov = hsig(go);
    const size_t cb = (size_t)px*COUT + ch;
    const float cold = FIRST ? 0.0f : g_c[cb];
    const float cn = fv*cold + iv*tanhf(gg);
    g_c[cb] = cn;
    const float hval = ov * tanhf(cn);

    __nv_bfloat16* nh_hi = (t & 1) ? g_h_hi1 : g_h_hi0;
    __nv_bfloat16* nh_lo = (t & 1) ? g_h_lo1 : g_h_lo0;
    const __nv_bfloat16 hh = __float2bfloat16(hval);
    nh_hi[(size_t)(GUARD + pad)*COUT + ch] = hh;
    nh_lo[(size_t)(GUARD + pad)*COUT + ch] = __float2bfloat16(hval - __bfloat162float(hh));

    const float inv = gamma[ch] * rsqrtf(mvar[ch] + 1e-3f);
    y[((size_t)(b*TT + t)*4096 + rem)*COUT + ch] = hval*inv + (beta[ch] - mmean[ch]*inv);
}

// ---------------- host ----------------------------------------------------------
extern "C" void kernel_launch(void* const* d_in, const int* in_sizes, int n_in,
                              void* d_out, int out_size)
{
    const float* x      = (const float*)d_in[0];
    const float* wk     = (const float*)d_in[1];
    const float* rw     = (const float*)d_in[2];
    const float* bias   = (const float*)d_in[3];
    const float* gamma  = (const float*)d_in[4];
    const float* beta   = (const float*)d_in[5];
    const float* mmean  = (const float*)d_in[6];
    const float* mvar   = (const float*)d_in[7];
    float* y = (float*)d_out;

    cudaFuncSetAttribute(step_gemm, cudaFuncAttributeMaxDynamicSharedMemorySize, GEMM_SMEM);
    cudaFuncSetAttribute(conv_gemm, cudaFuncAttributeMaxDynamicSharedMemorySize, CONV_SMEM);

    cudaStream_t s2;
    cudaStreamCreateWithFlags(&s2, cudaStreamNonBlocking);
    cudaEvent_t evPrep;
    cudaEvent_t evConv[4];
    cudaEventCreateWithFlags(&evPrep, cudaEventDisableTiming);
    for (int c = 0; c < 4; c++)
        cudaEventCreateWithFlags(&evConv[c], cudaEventDisableTiming);

    // Prep on main stream.
    prep_rw_bf16<<<(9*256*64)/256, 256>>>(rw);
    prep_wk_bf16<<<(9*256*32)/256, 256>>>(wk);
    prep_x<<<4096, 256>>>(x);
    cudaEventRecord(evPrep, 0);

    // Fork: input-conv GEMM in 4 chunks of 4 timesteps (560 tiles each) on s2.
    cudaStreamWaitEvent(s2, evPrep, 0);
    for (int c = 0; c < 4; c++) {
        conv_gemm<<<CHTILES, 512, CONV_SMEM, s2>>>(c*CHTILES);
        cudaEventRecord(evConv[c], s2);
    }

    // Main stream recurrence.
    const int epiBlocks = (BB*HH*WW*COUT)/256;   // 4096
    cudaStreamWaitEvent(0, evConv[0], 0);
    step_epi<true><<<epiBlocks, 256>>>(y, 0, bias, gamma, beta, mmean, mvar);
    for (int t = 1; t < TT; t++) {
        step_gemm<<<NTILE, 512, GEMM_SMEM>>>(t);
        if ((t & 3) == 0) cudaStreamWaitEvent(0, evConv[t >> 2], 0);
        step_epi<false><<<epiBlocks, 256>>>(y, t, bias, gamma, beta, mmean, mvar);
    }
}

// round 17
// speedup vs baseline: 1.7097x; 1.1261x over previous
#include <cuda_runtime.h>
#include <cuda_bf16.h>
#include <math.h>

#define BB 4
#define TT 16
#define HH 64
#define WW 64
#define CIN 32
#define COUT 64
#define GG 256

// Padded pixel space for the recurrent GEMM (h)
#define PW 66
#define PHW (PW*PW)            // 4356
#define PTOT (BB*PHW)          // 17424
#define NTILE 137              // ceil(17424/128)
#define PALLOC (NTILE*128)     // 17536
#define GUARD 128
#define HPX (PALLOC + 2*GUARD) // 17792

// Padded pixel space for the input-conv GEMM (x), t-major images, tile-aligned
#define PHW_AL 4480            // 35 tiles of 128
#define XIMG (BB*TT)           // 64 images
#define PALLOC_X (XIMG*PHW_AL) // 286720
#define XGUARD 128
#define XTILES (PALLOC_X/128)  // 2240
#define NCHUNK 8
#define CHTILES (XTILES/NCHUNK) // 280 tiles per 2-timestep chunk

typedef unsigned long long u64;
typedef unsigned int u32;

// ---------------- device scratch (zero-initialized) -------------------------
__device__ float g_gxp[(size_t)PALLOC_X*GG];          // input-conv gates, padded (fp32)
__device__ float g_rec[(size_t)PALLOC*GG];            // recurrent-conv gates (fp32)
__device__ float g_c  [(size_t)BB*HH*WW*COUT];        // cell state
// Ping-pong hidden state, padded, bf16 hi/lo split. Pads stay 0.
__device__ __align__(16) __nv_bfloat16 g_h_hi0[(size_t)HPX*COUT];
__device__ __align__(16) __nv_bfloat16 g_h_lo0[(size_t)HPX*COUT];
__device__ __align__(16) __nv_bfloat16 g_h_hi1[(size_t)HPX*COUT];
__device__ __align__(16) __nv_bfloat16 g_h_lo1[(size_t)HPX*COUT];
// Padded x, bf16 hi/lo split. Pads stay 0.
__device__ __align__(16) __nv_bfloat16 g_x_hi[(size_t)(PALLOC_X + 2*XGUARD)*CIN];
__device__ __align__(16) __nv_bfloat16 g_x_lo[(size_t)(PALLOC_X + 2*XGUARD)*CIN];
// Recurrent weights: [tap][n=256][k=64] bf16 hi/lo
__device__ __align__(16) __nv_bfloat16 g_Bhi[9*256*64];
__device__ __align__(16) __nv_bfloat16 g_Blo[9*256*64];
// Input weights: [tap][n=256][k=32] bf16 hi/lo
__device__ __align__(16) __nv_bfloat16 g_Whi[9*256*32];
__device__ __align__(16) __nv_bfloat16 g_Wlo[9*256*32];

// ---------------- helpers ----------------------------------------------------
__device__ __forceinline__ float hsig(float z) {
    return fminf(fmaxf(0.2f*z + 0.5f, 0.0f), 1.0f);
}
__device__ __forceinline__ u32 smem_to_u32(const void* p) {
    u32 a; asm("{ .reg .u64 t; cvta.to.shared.u64 t, %1; cvt.u32.u64 %0, t; }" : "=r"(a) : "l"(p));
    return a;
}

#define LDSM_X4(r0, r1, r2, r3, addr) \
    asm volatile("ldmatrix.sync.aligned.m8n8.x4.shared.b16 {%0,%1,%2,%3}, [%4];" \
        : "=r"(r0), "=r"(r1), "=r"(r2), "=r"(r3) : "r"(addr))

#define MMA_BF16(c, a, b) \
    asm volatile("mma.sync.aligned.m16n8k16.row.col.f32.bf16.bf16.f32 " \
        "{%0,%1,%2,%3}, {%4,%5,%6,%7}, {%8,%9}, {%0,%1,%2,%3};" \
        : "+f"((c)[0]), "+f"((c)[1]), "+f"((c)[2]), "+f"((c)[3]) \
        : "r"((a)[0]), "r"((a)[1]), "r"((a)[2]), "r"((a)[3]), \
          "r"((b)[0]), "r"((b)[1]))

#define CP_ASYNC16(dst, src) \
    asm volatile("cp.async.cg.shared.global [%0], [%1], 16;" :: "r"(dst), "l"(src))
#define CP_COMMIT() asm volatile("cp.async.commit_group;" ::: "memory")
#define CP_WAIT0() asm volatile("cp.async.wait_group 0;" ::: "memory")
#define CP_WAIT1() asm volatile("cp.async.wait_group 1;" ::: "memory")

// 128B-row swizzle (rec GEMM) and 64B-row swizzle (conv GEMM)
__device__ __forceinline__ u32 swz(u32 row, u32 chunk) {
    return row*128u + ((chunk ^ (row & 7u)) << 4);
}
__device__ __forceinline__ u32 swz32(u32 row, u32 chunk) {
    return row*64u + ((chunk ^ (row & 3u)) << 4);
}

// ---------------- prep kernels ------------------------------------------------
__global__ __launch_bounds__(256)
void prep_rw_bf16(const float* __restrict__ rw)
{
    const int i = blockIdx.x * 256 + threadIdx.x;
    if (i >= 9*256*64) return;
    const int k   = i & 63;
    const int n   = (i >> 6) & 255;
    const int tap = i >> 14;
    const float v = rw[((size_t)(tap*COUT + k))*GG + n];
    const __nv_bfloat16 h = __float2bfloat16(v);
    g_Bhi[i] = h;
    g_Blo[i] = __float2bfloat16(v - __bfloat162float(h));
}

__global__ __launch_bounds__(256)
void prep_wk_bf16(const float* __restrict__ wk)
{
    const int i = blockIdx.x * 256 + threadIdx.x;
    if (i >= 9*256*32) return;
    const int k   = i & 31;
    const int n   = (i >> 5) & 255;
    const int tap = i >> 13;
    const float v = wk[((size_t)(tap*CIN + k))*GG + n];
    const __nv_bfloat16 h = __float2bfloat16(v);
    g_Whi[i] = h;
    g_Wlo[i] = __float2bfloat16(v - __bfloat162float(h));
}

// x (fp32 NHWC, image idx b*TT+t) -> padded bf16 hi/lo, image idx t*BB+b
__global__ __launch_bounds__(256)
void prep_x(const float* __restrict__ x)
{
    const int gid = blockIdx.x * 256 + threadIdx.x;
    const int opx = gid >> 2;
    const int grp = gid & 3;
    const int bt  = opx >> 12;
    const int b   = bt >> 4;
    const int t   = bt & 15;
    const int rem = opx & 4095;
    const int yy  = rem >> 6, xx = rem & 63;
    const size_t dst = ((size_t)(XGUARD + (t*BB + b)*PHW_AL + (yy+1)*PW + (xx+1)))*CIN + grp*8;

    const float4 v0 = *(const float4*)(x + (size_t)opx*CIN + grp*8);
    const float4 v1 = *(const float4*)(x + (size_t)opx*CIN + grp*8 + 4);
    __nv_bfloat16 hi[8], lo[8];
    const float vs[8] = {v0.x, v0.y, v0.z, v0.w, v1.x, v1.y, v1.z, v1.w};
    #pragma unroll
    for (int j = 0; j < 8; j++) {
        hi[j] = __float2bfloat16(vs[j]);
        lo[j] = __float2bfloat16(vs[j] - __bfloat162float(hi[j]));
    }
    *(uint4*)(g_x_hi + dst) = *(const uint4*)hi;
    *(uint4*)(g_x_lo + dst) = *(const uint4*)lo;
}

// ---------------- input-conv HMMA GEMM (K=32, cp.async double-buffered B) ------
#define CA_HI 0
#define CA_LO 16896
#define CB_BASE 33792
#define CB_STRIDE 32768        // one buffer: hi (16384) + lo (16384)
#define CONV_SMEM (33792 + 2*CB_STRIDE)   // 99328

__global__ __launch_bounds__(512, 1)
void conv_gemm(const int gtile0)
{
    extern __shared__ char smem[];
    const u32 sbase = smem_to_u32(smem);
    const int tid  = threadIdx.x;
    const int wid  = tid >> 5;
    const int lane = tid & 31;
    const int m_base = (gtile0 + blockIdx.x) * 128;

    // A window fill (regular stores)
    for (int i = tid; i < 264*4; i += 512) {
        const int row = i >> 2, c = i & 3;
        const u32 d = swz32((u32)row, (u32)c);
        const size_t src = ((size_t)(XGUARD + m_base - 67 + row))*CIN + c*8;
        *(uint4*)(smem + CA_HI + d) = *(const uint4*)(g_x_hi + src);
        *(uint4*)(smem + CA_LO + d) = *(const uint4*)(g_x_lo + src);
    }

    // Prefetch B tap 0 into buffer 0
    #pragma unroll
    for (int i = tid; i < 256*4; i += 512) {
        const int row = i >> 2, c = i & 3;
        const u32 d = swz32((u32)row, (u32)c);
        const size_t src = (size_t)row*CIN + c*8;
        CP_ASYNC16(sbase + CB_BASE + d,         (const char*)(g_Whi + src));
        CP_ASYNC16(sbase + CB_BASE + 16384 + d, (const char*)(g_Wlo + src));
    }
    CP_COMMIT();

    const int wm = wid >> 3;
    const int wn = wid & 7;
    const int n0 = wn * 32;
    const int lmat = lane >> 3;
    const int lrow = lane & 7;
    const int aRowLane  = wm*64 + 67 + (lmat & 1)*8 + lrow;
    const int aChunkSel = lmat >> 1;
    const int bRowLane  = n0 + (lmat >> 1)*8 + lrow;
    const int bChunkSel = lmat & 1;

    float acc[4][4][4];
    #pragma unroll
    for (int ms = 0; ms < 4; ms++)
        #pragma unroll
        for (int nf = 0; nf < 4; nf++)
            #pragma unroll
            for (int e = 0; e < 4; e++) acc[ms][nf][e] = 0.0f;

    const int aoff[9] = {-PW-1, -PW, -PW+1, -1, 0, 1, PW-1, PW, PW+1};
    int cur = 0;

    #pragma unroll 1
    for (int tap = 0; tap < 9; tap++) {
        if (tap < 8) {
            const u32 dbase = sbase + CB_BASE + (cur^1)*CB_STRIDE;
            #pragma unroll
            for (int i = tid; i < 256*4; i += 512) {
                const int row = i >> 2, c = i & 3;
                const u32 d = swz32((u32)row, (u32)c);
                const size_t src = (size_t)(tap+1)*8192 + (size_t)row*CIN + c*8;
                CP_ASYNC16(dbase + d,         (const char*)(g_Whi + src));
                CP_ASYNC16(dbase + 16384 + d, (const char*)(g_Wlo + src));
            }
            CP_COMMIT();
            CP_WAIT1();
        } else {
            CP_WAIT0();
        }
        __syncthreads();

        const u32 bHi = sbase + CB_BASE + cur*CB_STRIDE;
        const u32 bLo = bHi + 16384;

        #pragma unroll
        for (int kc = 0; kc < 2; kc++) {
            u32 ah[4][4];
            #pragma unroll
            for (int ms = 0; ms < 4; ms++) {
                const int wrow = aRowLane + ms*16 + aoff[tap];
                const u32 addr = sbase + CA_HI + swz32((u32)wrow, (u32)(2*kc + aChunkSel));
                LDSM_X4(ah[ms][0], ah[ms][1], ah[ms][2], ah[ms][3], addr);
            }
            u32 bhi[4][2], blo[4][2];
            #pragma unroll
            for (int q = 0; q < 2; q++) {
                const u32 addr = bHi + swz32((u32)(bRowLane + q*16), (u32)(2*kc + bChunkSel));
                LDSM_X4(bhi[2*q][0], bhi[2*q][1], bhi[2*q+1][0], bhi[2*q+1][1], addr);
            }
            #pragma unroll
            for (int ms = 0; ms < 4; ms++)
                #pragma unroll
                for (int nf = 0; nf < 4; nf++)
                    MMA_BF16(acc[ms][nf], ah[ms], bhi[nf]);
            #pragma unroll
            for (int q = 0; q < 2; q++) {
                const u32 addr = bLo + swz32((u32)(bRowLane + q*16), (u32)(2*kc + bChunkSel));
                LDSM_X4(blo[2*q][0], blo[2*q][1], blo[2*q+1][0], blo[2*q+1][1], addr);
            }
            #pragma unroll
            for (int ms = 0; ms < 4; ms++)
                #pragma unroll
                for (int nf = 0; nf < 4; nf++)
                    MMA_BF16(acc[ms][nf], ah[ms], blo[nf]);
            // A_lo pass reusing resident bhi
            #pragma unroll
            for (int ms = 0; ms < 4; ms++) {
                const int wrow = aRowLane + ms*16 + aoff[tap];
                const u32 addr = sbase + CA_LO + swz32((u32)wrow, (u32)(2*kc + aChunkSel));
                LDSM_X4(ah[ms][0], ah[ms][1], ah[ms][2], ah[ms][3], addr);
            }
            #pragma unroll
            for (int ms = 0; ms < 4; ms++)
                #pragma unroll
                for (int nf = 0; nf < 4; nf++)
                    MMA_BF16(acc[ms][nf], ah[ms], bhi[nf]);
        }
        __syncthreads();   // all reads of buffer 'cur' done before refill
        cur ^= 1;
    }

    const int rbase = m_base + wm*64 + (lane >> 2);
    const int cbase = n0 + (lane & 3)*2;
    #pragma unroll
    for (int ms = 0; ms < 4; ms++) {
        #pragma unroll
        for (int nf = 0; nf < 4; nf++) {
            float* p0 = g_gxp + (size_t)(rbase + ms*16    )*GG + cbase + nf*8;
            float* p1 = g_gxp + (size_t)(rbase + ms*16 + 8)*GG + cbase + nf*8;
            *(float2*)p0 = make_float2(acc[ms][nf][0], acc[ms][nf][1]);
            *(float2*)p1 = make_float2(acc[ms][nf][2], acc[ms][nf][3]);
        }
    }
}

// ---------------- recurrent HMMA GEMM (cp.async double-buffered B) -------------
#define SM_A_HI 0
#define SM_A_LO 33792
#define SM_B_BASE 67584
#define SM_B_STRIDE 65536      // one buffer: hi (32768) + lo (32768)
#define GEMM_SMEM (67584 + 2*SM_B_STRIDE)   // 198656

__global__ __launch_bounds__(512, 1)
void step_gemm(const int t)
{
    extern __shared__ char smem[];
    const u32 sbase = smem_to_u32(smem);
    const int tid  = threadIdx.x;
    const int wid  = tid >> 5;
    const int lane = tid & 31;
    const int m_base = blockIdx.x * 128;

    const __nv_bfloat16* __restrict__ ph_hi = (t & 1) ? g_h_hi0 : g_h_hi1;
    const __nv_bfloat16* __restrict__ ph_lo = (t & 1) ? g_h_lo0 : g_h_lo1;

    // A window fill
    {
        const size_t src0 = (size_t)(GUARD + m_base - 67) * COUT;
        for (int i = tid; i < 264*8; i += 512) {
            const int row = i >> 3, c = i & 7;
            const u32 d = swz((u32)row, (u32)c);
            *(uint4*)(smem + SM_A_HI + d) =
                *(const uint4*)(ph_hi + src0 + (size_t)row*COUT + c*8);
            *(uint4*)(smem + SM_A_LO + d) =
                *(const uint4*)(ph_lo + src0 + (size_t)row*COUT + c*8);
        }
    }

    // Prefetch B tap 0 into buffer 0
    #pragma unroll
    for (int i = tid; i < 256*8; i += 512) {
        const int row = i >> 3, c = i & 7;
        const u32 d = swz((u32)row, (u32)c);
        const size_t src = (size_t)row*64 + c*8;
        CP_ASYNC16(sbase + SM_B_BASE + d,         (const char*)(g_Bhi + src));
        CP_ASYNC16(sbase + SM_B_BASE + 32768 + d, (const char*)(g_Blo + src));
    }
    CP_COMMIT();

    const int wm = wid >> 3;
    const int wn = wid & 7;
    const int n0 = wn * 32;
    const int lmat = lane >> 3;
    const int lrow = lane & 7;
    const int aRowLane  = wm*64 + 67 + (lmat & 1)*8 + lrow;
    const int aChunkSel = lmat >> 1;
    const int bRowLane  = n0 + (lmat >> 1)*8 + lrow;
    const int bChunkSel = lmat & 1;

    float acc[4][4][4];
    #pragma unroll
    for (int ms = 0; ms < 4; ms++)
        #pragma unroll
        for (int nf = 0; nf < 4; nf++)
            #pragma unroll
            for (int e = 0; e < 4; e++) acc[ms][nf][e] = 0.0f;

    const int aoff[9] = {-PW-1, -PW, -PW+1, -1, 0, 1, PW-1, PW, PW+1};
    int cur = 0;

    #pragma unroll 1
    for (int tap = 0; tap < 9; tap++) {
        if (tap < 8) {
            const u32 dbase = sbase + SM_B_BASE + (cur^1)*SM_B_STRIDE;
            #pragma unroll
            for (int i = tid; i < 256*8; i += 512) {
                const int row = i >> 3, c = i & 7;
                const u32 d = swz((u32)row, (u32)c);
                const size_t src = (size_t)(tap+1)*16384 + (size_t)row*64 + c*8;
                CP_ASYNC16(dbase + d,         (const char*)(g_Bhi + src));
                CP_ASYNC16(dbase + 32768 + d, (const char*)(g_Blo + src));
            }
            CP_COMMIT();
            CP_WAIT1();
        } else {
            CP_WAIT0();
        }
        __syncthreads();

        const u32 bHi = sbase + SM_B_BASE + cur*SM_B_STRIDE;
        const u32 bLo = bHi + 32768;

        #pragma unroll
        for (int kc = 0; kc < 4; kc++) {
            u32 ah[4][4];
            #pragma unroll
            for (int ms = 0; ms < 4; ms++) {
                const int wrow = aRowLane + ms*16 + aoff[tap];
                const u32 addr = sbase + SM_A_HI + swz((u32)wrow, (u32)(2*kc + aChunkSel));
                LDSM_X4(ah[ms][0], ah[ms][1], ah[ms][2], ah[ms][3], addr);
            }
            u32 bhi[4][2], blo[4][2];
            #pragma unroll
            for (int q = 0; q < 2; q++) {
                const u32 addr = bHi + swz((u32)(bRowLane + q*16), (u32)(2*kc + bChunkSel));
                LDSM_X4(bhi[2*q][0], bhi[2*q][1], bhi[2*q+1][0], bhi[2*q+1][1], addr);
            }
            #pragma unroll
            for (int ms = 0; ms < 4; ms++)
                #pragma unroll
                for (int nf = 0; nf < 4; nf++)
                    MMA_BF16(acc[ms][nf], ah[ms], bhi[nf]);
            #pragma unroll
            for (int q = 0; q < 2; q++) {
                const u32 addr = bLo + swz((u32)(bRowLane + q*16), (u32)(2*kc + bChunkSel));
                LDSM_X4(blo[2*q][0], blo[2*q][1], blo[2*q+1][0], blo[2*q+1][1], addr);
            }
            #pragma unroll
            for (int ms = 0; ms < 4; ms++)
                #pragma unroll
                for (int nf = 0; nf < 4; nf++)
                    MMA_BF16(acc[ms][nf], ah[ms], blo[nf]);
            #pragma unroll
            for (int ms = 0; ms < 4; ms++) {
                const int wrow = aRowLane + ms*16 + aoff[tap];
                const u32 addr = sbase + SM_A_LO + swz((u32)wrow, (u32)(2*kc + aChunkSel));
                LDSM_X4(ah[ms][0], ah[ms][1], ah[ms][2], ah[ms][3], addr);
            }
            #pragma unroll
            for (int ms = 0; ms < 4; ms++)
                #pragma unroll
                for (int nf = 0; nf < 4; nf++)
                    MMA_BF16(acc[ms][nf], ah[ms], bhi[nf]);
        }
        __syncthreads();
        cur ^= 1;
    }

    const int rbase = m_base + wm*64 + (lane >> 2);
    const int cbase = n0 + (lane & 3)*2;
    #pragma unroll
    for (int ms = 0; ms < 4; ms++) {
        #pragma unroll
        for (int nf = 0; nf < 4; nf++) {
            float* p0 = g_rec + (size_t)(rbase + ms*16    )*GG + cbase + nf*8;
            float* p1 = g_rec + (size_t)(rbase + ms*16 + 8)*GG + cbase + nf*8;
            *(float2*)p0 = make_float2(acc[ms][nf][0], acc[ms][nf][1]);
            *(float2*)p1 = make_float2(acc[ms][nf][2], acc[ms][nf][3]);
        }
    }
}

// ---------------- LSTM epilogue (high-occupancy) --------------------------------
template<bool FIRST>
__global__ __launch_bounds__(256)
void step_epi(float* __restrict__ y, const int t,
              const float* __restrict__ bias,
              const float* __restrict__ gamma, const float* __restrict__ beta,
              const float* __restrict__ mmean, const float* __restrict__ mvar)
{
    const int gid = blockIdx.x * 256 + threadIdx.x;
    const int px  = gid >> 6;
    const int ch  = gid & 63;
    const int b   = px >> 12;
    const int rem = px & 4095;
    const int yy  = rem >> 6, xx = rem & 63;
    const int pind = (yy + 1)*PW + (xx + 1);
    const int pad  = b*PHW + pind;

    const size_t gxb = ((size_t)(t*BB + b)*PHW_AL + pind)*GG + ch;
    float gi = g_gxp[gxb + 0*COUT] + bias[0*COUT + ch];
    float gf = g_gxp[gxb + 1*COUT] + bias[1*COUT + ch];
    float gg = g_gxp[gxb + 2*COUT] + bias[2*COUT + ch];
    float go = g_gxp[gxb + 3*COUT] + bias[3*COUT + ch];
    if (!FIRST) {
        const size_t rb = (size_t)pad*GG + ch;
        gi += g_rec[rb + 0*COUT];
        gf += g_rec[rb + 1*COUT];
        gg += g_rec[rb + 2*COUT];
        go += g_rec[rb + 3*COUT];
    }
    const float iv = hsig(gi), fv = hsig(gf), ov = hsig(go);
    const size_t cb = (size_t)px*COUT + ch;
    const float cold = FIRST ? 0.0f : g_c[cb];
    const float cn = fv*cold + iv*tanhf(gg);
    g_c[cb] = cn;
    const float hval = ov * tanhf(cn);

    __nv_bfloat16* nh_hi = (t & 1) ? g_h_hi1 : g_h_hi0;
    __nv_bfloat16* nh_lo = (t & 1) ? g_h_lo1 : g_h_lo0;
    const __nv_bfloat16 hh = __float2bfloat16(hval);
    nh_hi[(size_t)(GUARD + pad)*COUT + ch] = hh;
    nh_lo[(size_t)(GUARD + pad)*COUT + ch] = __float2bfloat16(hval - __bfloat162float(hh));

    const float inv = gamma[ch] * rsqrtf(mvar[ch] + 1e-3f);
    y[((size_t)(b*TT + t)*4096 + rem)*COUT + ch] = hval*inv + (beta[ch] - mmean[ch]*inv);
}

// ---------------- host ----------------------------------------------------------
extern "C" void kernel_launch(void* const* d_in, const int* in_sizes, int n_in,
                              void* d_out, int out_size)
{
    const float* x      = (const float*)d_in[0];
    const float* wk     = (const float*)d_in[1];
    const float* rw     = (const float*)d_in[2];
    const float* bias   = (const float*)d_in[3];
    const float* gamma  = (const float*)d_in[4];
    const float* beta   = (const float*)d_in[5];
    const float* mmean  = (const float*)d_in[6];
    const float* mvar   = (const float*)d_in[7];
    float* y = (float*)d_out;

    cudaFuncSetAttribute(step_gemm, cudaFuncAttributeMaxDynamicSharedMemorySize, GEMM_SMEM);
    cudaFuncSetAttribute(conv_gemm, cudaFuncAttributeMaxDynamicSharedMemorySize, CONV_SMEM);

    cudaStream_t s2;
    cudaStreamCreateWithFlags(&s2, cudaStreamNonBlocking);
    cudaEvent_t evPrep;
    cudaEvent_t evConv[NCHUNK];
    cudaEventCreateWithFlags(&evPrep, cudaEventDisableTiming);
    for (int c = 0; c < NCHUNK; c++)
        cudaEventCreateWithFlags(&evConv[c], cudaEventDisableTiming);

    // Prep on main stream.
    prep_rw_bf16<<<(9*256*64)/256, 256>>>(rw);
    prep_wk_bf16<<<(9*256*32)/256, 256>>>(wk);
    prep_x<<<4096, 256>>>(x);
    cudaEventRecord(evPrep, 0);

    // Fork: input-conv GEMM in 8 chunks of 2 timesteps (280 tiles each) on s2.
    cudaStreamWaitEvent(s2, evPrep, 0);
    for (int c = 0; c < NCHUNK; c++) {
        conv_gemm<<<CHTILES, 512, CONV_SMEM, s2>>>(c*CHTILES);
        cudaEventRecord(evConv[c], s2);
    }

    // Main stream recurrence.
    const int epiBlocks = (BB*HH*WW*COUT)/256;   // 4096
    cudaStreamWaitEvent(0, evConv[0], 0);
    step_epi<true><<<epiBlocks, 256>>>(y, 0, bias, gamma, beta, mmean, mvar);
    for (int t = 1; t < TT; t++) {
        step_gemm<<<NTILE, 512, GEMM_SMEM>>>(t);
        if ((t & 1) == 0) cudaStreamWaitEvent(0, evConv[t >> 1], 0);
        step_epi<false><<<epiBlocks, 256>>>(y, t, bias, gamma, beta, mmean, mvar);
    }
}